// round 12
// baseline (speedup 1.0000x reference)
#include <cuda_runtime.h>
#include <math.h>

#define DIM   1024
#define NC    8
#define NPER  4096
#define QDIM  128
#define TOPK  128
#define HBITS 12
#define HBINS (1 << HBITS)      // 4096 bins per cluster
#define CANDMAX 640
#define STAGE_BYTES 32768       // 8 rows * 4KB
#define ROWS_PER_BLK 16
#define NSTAGE (ROWS_PER_BLK / 8)   // 2
#define BLKS_PER_C (NPER / ROWS_PER_BLK)  // 256

// Scratch (no allocations allowed -> __device__ globals)
__device__ float g_w[NC][DIM];                   // q_w^T @ qk per cluster
__device__ float g_b0[NC];                       // q_b . qk
__device__ unsigned long long g_keys[NC][NPER];  // (desc-map(score)<<32)|idx
__device__ unsigned g_hist[NC][HBINS];           // 12-bit key-prefix histogram
__device__ int   g_topidx[NC][TOPK];             // sorted top-k indices
__device__ float g_gvec[NC][DIM];                // sum_n e^{s_n} feats[n]
__device__ float g_Z[NC];                        // sum_n e^{s_n}

// ---------------------------------------------------------------------------
// cp.async helpers
// ---------------------------------------------------------------------------
__device__ __forceinline__ void cp_async16(unsigned saddr, const void* gaddr) {
    asm volatile("cp.async.cg.shared.global [%0], [%1], 16;"
                 :: "r"(saddr), "l"(gaddr));
}
__device__ __forceinline__ void cp_commit() {
    asm volatile("cp.async.commit_group;");
}
template <int N>
__device__ __forceinline__ void cp_wait() {
    asm volatile("cp.async.wait_group %0;" :: "n"(N));
}

// ---------------------------------------------------------------------------
// Kernel A: per-cluster qk = key@q_w^T + q_b ; w = q_w^T @ qk ; b0 = q_b.qk
// Also zeroes g_gvec / g_Z / g_hist. grid = NC, block = 1024.
// ---------------------------------------------------------------------------
__global__ __launch_bounds__(1024) void prep_kernel(const float* __restrict__ key_feats,
                                                    const float* __restrict__ q_w,
                                                    const float* __restrict__ q_b) {
    __shared__ __align__(16) float s_qk[QDIM];
    __shared__ float red[4];
    int c = blockIdx.x;
    int t = threadIdx.x;
    int warp = t >> 5, lane = t & 31;

    g_gvec[c][t] = 0.f;          // t covers all DIM=1024
    if (t == 0) g_Z[c] = 0.f;

    // zero this cluster's histogram (4096 bins = 1024 uint4)
    ((uint4*)g_hist[c])[t] = make_uint4(0u, 0u, 0u, 0u);

    const float4* kr = (const float4*)(key_feats + (size_t)c * DIM);
    #pragma unroll
    for (int rr = 0; rr < 4; rr++) {
        int q = warp + rr * 32;
        const float4* qr = (const float4*)(q_w + (size_t)q * DIM);
        float a = 0.f;
        #pragma unroll
        for (int k = 0; k < 8; k++) {
            float4 x = qr[lane + k * 32], y = kr[lane + k * 32];
            a += x.x * y.x + x.y * y.y + x.z * y.z + x.w * y.w;
        }
        #pragma unroll
        for (int o = 16; o > 0; o >>= 1)
            a += __shfl_xor_sync(0xffffffffu, a, o);
        if (lane == 0) s_qk[q] = a + q_b[q];
    }
    __syncthreads();

    float wacc = 0.f;
    #pragma unroll 16
    for (int q = 0; q < QDIM; q++)
        wacc += s_qk[q] * q_w[(size_t)q * DIM + t];
    g_w[c][t] = wacc;

    if (t < QDIM) {
        float p = s_qk[t] * q_b[t];
        #pragma unroll
        for (int o = 16; o > 0; o >>= 1)
            p += __shfl_xor_sync(0xffffffffu, p, o);
        if (lane == 0) red[warp] = p;
    }
    __syncthreads();
    if (t == 0) g_b0[c] = red[0] + red[1] + red[2] + red[3];
}

// ---------------------------------------------------------------------------
// Kernel B (cp.async pipeline, finer granularity):
// block = 256 (8 warps), 16 rows/block in 2 stages of 8 rows.
// grid = NC*256 = 2048 blocks (4.6 waves -> smooth tail).
// Stage n+1 DMA'd while stage n consumed from smem.
// ---------------------------------------------------------------------------
__global__ __launch_bounds__(256) void fused_pass_kernel(const float* __restrict__ feats) {
    __shared__ __align__(16) float sw[DIM];
    __shared__ float se[8];
    extern __shared__ __align__(16) float buf[];   // 2 * 8192 floats

    int bid = blockIdx.x;
    int c = bid >> 8;                       // 256 blocks per cluster
    int base = (bid & (BLKS_PER_C - 1)) * ROWS_PER_BLK;
    int t = threadIdx.x, warp = t >> 5, lane = t & 31;

    ((float4*)sw)[t] = ((const float4*)(g_w[c]))[t];
    float b0 = g_b0[c];

    const char* gbase =
        (const char*)(feats + ((size_t)c * NPER + base) * DIM);
    unsigned sbuf = (unsigned)__cvta_generic_to_shared(buf);

    // prefetch stage 0 into buffer 0
    {
        unsigned s0 = sbuf + (unsigned)t * 16u;
        const char* g0 = gbase + t * 16;
        #pragma unroll
        for (int i = 0; i < 8; i++)
            cp_async16(s0 + i * 4096u, g0 + i * 4096);
        cp_commit();
    }

    float4 acc = make_float4(0.f, 0.f, 0.f, 0.f);
    float zw = 0.f;   // meaningful in thread 0 only

    #pragma unroll
    for (int st = 0; st < NSTAGE; st++) {
        if (st < NSTAGE - 1) {
            unsigned sb = sbuf + (unsigned)(((st + 1) & 1) * STAGE_BYTES)
                        + (unsigned)t * 16u;
            const char* gb = gbase + (size_t)(st + 1) * STAGE_BYTES + t * 16;
            #pragma unroll
            for (int i = 0; i < 8; i++)
                cp_async16(sb + i * 4096u, gb + i * 4096);
            cp_commit();
            cp_wait<1>();    // stage st complete
        } else {
            cp_wait<0>();
        }
        __syncthreads();

        const float* sb = buf + (st & 1) * (STAGE_BYTES / 4);

        // warp w: dot of row w vs sw
        {
            const float4* fr = (const float4*)(sb + warp * DIM);
            const float4* wr = (const float4*)sw;
            float d = 0.f;
            #pragma unroll
            for (int k = 0; k < 8; k++) {
                float4 a = fr[lane + k * 32], w4 = wr[lane + k * 32];
                d += a.x * w4.x + a.y * w4.y + a.z * w4.z + a.w * w4.w;
            }
            #pragma unroll
            for (int o = 16; o > 0; o >>= 1)
                d += __shfl_xor_sync(0xffffffffu, d, o);
            if (lane == 0) {
                float s = (d + b0) * 0.08838834764831845f;  // 1/sqrt(128)
                float e = expf(s);                           // |s| small: safe
                se[warp] = e;
                int n = base + st * 8 + warp;
                unsigned u = __float_as_uint(s);
                u = (u & 0x80000000u) ? ~u : (u | 0x80000000u);  // asc map
                unsigned dm = ~u;                                // desc map
                g_keys[c][n] = ((unsigned long long)dm << 32) | (unsigned)n;
                atomicAdd(&g_hist[c][dm >> (32 - HBITS)], 1u);
            }
        }
        __syncthreads();

        // thread t owns col4 t: accumulate 8 weighted rows
        const float4* bb = (const float4*)sb;
        #pragma unroll
        for (int r = 0; r < 8; r++) {
            float e = se[r];
            float4 f = bb[r * 256 + t];
            acc.x += e * f.x; acc.y += e * f.y;
            acc.z += e * f.z; acc.w += e * f.w;
        }
        if (t == 0) {
            #pragma unroll
            for (int r = 0; r < 8; r++) zw += se[r];
        }
        __syncthreads();
    }

    float* gp = g_gvec[c] + t * 4;
    atomicAdd(gp + 0, acc.x);
    atomicAdd(gp + 1, acc.y);
    atomicAdd(gp + 2, acc.z);
    atomicAdd(gp + 3, acc.w);
    if (t == 0) atomicAdd(&g_Z[c], zw);
}

// ---------------------------------------------------------------------------
// Kernel C: exact top-128 via precomputed 12-bit histogram.
// grid = NC, block = 1024.
// ---------------------------------------------------------------------------
__global__ __launch_bounds__(1024) void topk_kernel() {
    __shared__ unsigned warp_tot[32];
    __shared__ unsigned warp_off[32];
    __shared__ unsigned s_B, s_total;
    __shared__ unsigned long long cand[CANDMAX];

    int c = blockIdx.x;
    int t = threadIdx.x;
    int warp = t >> 5, lane = t & 31;

    // ---- 1. histogram scan: find bin B where cumulative count >= 128 ----
    unsigned bins[4];
    {
        uint4 q = ((const uint4*)g_hist[c])[t];
        bins[0] = q.x; bins[1] = q.y; bins[2] = q.z; bins[3] = q.w;
    }
    unsigned loc = bins[0] + bins[1] + bins[2] + bins[3];

    unsigned incl = loc;
    #pragma unroll
    for (int o = 1; o < 32; o <<= 1) {
        unsigned u = __shfl_up_sync(0xffffffffu, incl, o);
        if (lane >= o) incl += u;
    }
    if (lane == 31) warp_tot[warp] = incl;
    __syncthreads();
    if (warp == 0) {
        unsigned v = warp_tot[lane];
        unsigned i2 = v;
        #pragma unroll
        for (int o = 1; o < 32; o <<= 1) {
            unsigned u = __shfl_up_sync(0xffffffffu, i2, o);
            if (lane >= o) i2 += u;
        }
        warp_off[lane] = i2 - v;   // exclusive per-warp offset
    }
    __syncthreads();

    unsigned texcl = warp_off[warp] + incl - loc;  // excl prefix before my bins
    if (texcl < TOPK && texcl + loc >= TOPK) {     // crossing in my 4 bins
        unsigned run = texcl;
        #pragma unroll
        for (int i = 0; i < 4; i++) {
            run += bins[i];
            if (run >= TOPK) { s_B = (unsigned)(t * 4 + i); s_total = run; break; }
        }
    }
    __syncthreads();
    unsigned B = s_B;

    // ---- 2. compact candidates (prefix <= B) via ballot-scan ----
    unsigned long long key[4];
    bool sel[4];
    unsigned laneoff[4];
    unsigned cnt_w = 0u;
    #pragma unroll
    for (int i = 0; i < 4; i++) {
        key[i] = g_keys[c][t + i * 1024];
        sel[i] = ((unsigned)(key[i] >> (64 - HBITS)) <= B);
        unsigned b = __ballot_sync(0xffffffffu, sel[i]);
        laneoff[i] = cnt_w + __popc(b & ((1u << lane) - 1u));
        cnt_w += __popc(b);
    }
    if (lane == 0) warp_tot[warp] = cnt_w;
    __syncthreads();
    if (warp == 0) {
        unsigned v = warp_tot[lane];
        unsigned i2 = v;
        #pragma unroll
        for (int o = 1; o < 32; o <<= 1) {
            unsigned u = __shfl_up_sync(0xffffffffu, i2, o);
            if (lane >= o) i2 += u;
        }
        warp_off[lane] = i2 - v;
    }
    __syncthreads();
    unsigned cbase = warp_off[warp];
    #pragma unroll
    for (int i = 0; i < 4; i++) {
        if (sel[i]) {
            unsigned p = cbase + laneoff[i];
            if (p < CANDMAX) cand[p] = key[i];
        }
    }
    __syncthreads();

    // ---- 3. rank-by-counting (candidate rank == global rank) ----
    unsigned cnt = s_total < CANDMAX ? s_total : CANDMAX;
    if (t < cnt) {
        unsigned long long mine = cand[t];
        unsigned rank = 0u;
        for (unsigned j = 0; j < cnt; j++)
            rank += (cand[j] < mine) ? 1u : 0u;
        if (rank < TOPK)
            g_topidx[c][rank] = (int)(unsigned)(mine & 0xffffffffu);
    }
}

// ---------------------------------------------------------------------------
// Kernel D (merged gather + fusion), block = 256. UNCHANGED.
// This is the 4th launch -> ncu capture slot this round.
// ---------------------------------------------------------------------------
__global__ __launch_bounds__(256) void gather_fusion_kernel(
        const float* __restrict__ feats,
        const float* __restrict__ v_w,
        const float* __restrict__ v_b,
        float* __restrict__ out) {
    __shared__ __align__(16) float sg[DIM];
    int t = threadIdx.x;

    if (blockIdx.x < 1024) {
        int row = blockIdx.x;
        int c = row >> 7, k = row & 127;
        int src = g_topidx[c][k];
        const float4* s =
            (const float4*)(feats + ((size_t)c * NPER + src) * DIM);
        float4* dst = (float4*)(out + (size_t)row * DIM);
        dst[t] = s[t];
        return;
    }

    int bid = blockIdx.x - 1024;   // 0..1023
    int c = bid >> 7;
    int o0 = (bid & 127) * 8;

    float invZ = 1.f / g_Z[c];
    float4 gv = ((const float4*)(g_gvec[c]))[t];
    gv.x *= invZ; gv.y *= invZ; gv.z *= invZ; gv.w *= invZ;
    ((float4*)sg)[t] = gv;
    __syncthreads();

    int warp = t >> 5, lane = t & 31;
    int o = o0 + warp;
    const float4* vr = (const float4*)(v_w + (size_t)o * DIM);
    const float4* gr = (const float4*)sg;
    float acc = 0.f;
    #pragma unroll
    for (int i = 0; i < 8; i++) {
        int idx = lane + i * 32;
        float4 a = vr[idx], b = gr[idx];
        acc += a.x * b.x + a.y * b.y + a.z * b.z + a.w * b.w;
    }
    #pragma unroll
    for (int ofs = 16; ofs > 0; ofs >>= 1)
        acc += __shfl_xor_sync(0xffffffffu, acc, ofs);
    if (lane == 0)
        out[(size_t)1024 * 1024 + (size_t)c * DIM + o] = acc + v_b[o];
}

// ---------------------------------------------------------------------------
extern "C" void kernel_launch(void* const* d_in, const int* in_sizes, int n_in,
                              void* d_out, int out_size) {
    const float* feats     = (const float*)d_in[0];  // [8,4096,1024]
    const float* key_feats = (const float*)d_in[1];  // [8,1,1024]
    const float* q_w       = (const float*)d_in[2];  // [128,1024]
    const float* q_b       = (const float*)d_in[3];  // [128]
    const float* v_w       = (const float*)d_in[4];  // [1024,1024]
    const float* v_b       = (const float*)d_in[5];  // [1024]
    float* out = (float*)d_out;  // selected [1024,1024] then fus [8,1024]

    static bool attr_done = false;
    if (!attr_done) {
        cudaFuncSetAttribute(fused_pass_kernel,
                             cudaFuncAttributeMaxDynamicSharedMemorySize,
                             2 * STAGE_BYTES);
        attr_done = true;
    }

    prep_kernel<<<NC, 1024>>>(key_feats, q_w, q_b);
    fused_pass_kernel<<<NC * BLKS_PER_C, 256, 2 * STAGE_BYTES>>>(feats);
    topk_kernel<<<NC, 1024>>>();
    gather_fusion_kernel<<<2048, 256>>>(feats, v_w, v_b, out);  // profiled
}

// round 13
// speedup vs baseline: 1.2826x; 1.2826x over previous
#include <cuda_runtime.h>
#include <math.h>

#define DIM   1024
#define NC    8
#define NPER  4096
#define QDIM  128
#define TOPK  128
#define HBITS 12
#define HBINS (1 << HBITS)      // 4096 bins per cluster
#define CANDMAX 640

// Scratch (no allocations allowed -> __device__ globals)
__device__ float g_w[NC][DIM];                   // q_w^T @ qk per cluster
__device__ float g_b0[NC];                       // q_b . qk
__device__ unsigned long long g_keys[NC][NPER];  // (desc-map(score)<<32)|idx
__device__ unsigned g_hist[NC][HBINS];           // 12-bit key-prefix histogram
__device__ int   g_topidx[NC][TOPK];             // sorted top-k indices
__device__ float g_gvec[NC][DIM];                // sum_n e^{s_n} feats[n]
__device__ float g_Z[NC];                        // sum_n e^{s_n}

// ---------------------------------------------------------------------------
// Kernel A: per-cluster qk = key@q_w^T + q_b ; w = q_w^T @ qk ; b0 = q_b.qk
// Also zeroes g_gvec / g_Z / g_hist. grid = NC, block = 1024.
// ---------------------------------------------------------------------------
__global__ __launch_bounds__(1024) void prep_kernel(const float* __restrict__ key_feats,
                                                    const float* __restrict__ q_w,
                                                    const float* __restrict__ q_b) {
    __shared__ __align__(16) float s_qk[QDIM];
    __shared__ float red[4];
    int c = blockIdx.x;
    int t = threadIdx.x;
    int warp = t >> 5, lane = t & 31;

    g_gvec[c][t] = 0.f;          // t covers all DIM=1024
    if (t == 0) g_Z[c] = 0.f;

    // zero this cluster's histogram (4096 bins = 1024 uint4)
    ((uint4*)g_hist[c])[t] = make_uint4(0u, 0u, 0u, 0u);

    const float4* kr = (const float4*)(key_feats + (size_t)c * DIM);
    #pragma unroll
    for (int rr = 0; rr < 4; rr++) {
        int q = warp + rr * 32;
        const float4* qr = (const float4*)(q_w + (size_t)q * DIM);
        float a = 0.f;
        #pragma unroll
        for (int k = 0; k < 8; k++) {
            float4 x = qr[lane + k * 32], y = kr[lane + k * 32];
            a += x.x * y.x + x.y * y.y + x.z * y.z + x.w * y.w;
        }
        #pragma unroll
        for (int o = 16; o > 0; o >>= 1)
            a += __shfl_xor_sync(0xffffffffu, a, o);
        if (lane == 0) s_qk[q] = a + q_b[q];
    }
    __syncthreads();

    float wacc = 0.f;
    #pragma unroll 16
    for (int q = 0; q < QDIM; q++)
        wacc += s_qk[q] * q_w[(size_t)q * DIM + t];
    g_w[c][t] = wacc;

    if (t < QDIM) {
        float p = s_qk[t] * q_b[t];
        #pragma unroll
        for (int o = 16; o > 0; o >>= 1)
            p += __shfl_xor_sync(0xffffffffu, p, o);
        if (lane == 0) red[warp] = p;
    }
    __syncthreads();
    if (t == 0) g_b0[c] = red[0] + red[1] + red[2] + red[3];
}

// ---------------------------------------------------------------------------
// Kernel B: EXACT R9 fused pass (best measured: ~31.9us).
// warp owns a row: 8 float4/lane, dot vs w (smem), s -> key + hist,
// e = exp(s), acc += e*row (registers). Block-combine + global atomics.
// grid = NC*64 (64 rows/block), block = 256 (8 warps x 8 rows each).
// ---------------------------------------------------------------------------
__global__ __launch_bounds__(256) void fused_pass_kernel(const float* __restrict__ feats) {
    __shared__ __align__(16) float sw[DIM];
    __shared__ __align__(16) float sacc[DIM];
    __shared__ float zsh;

    int bid = blockIdx.x;
    int c = bid >> 6;
    int base = (bid & 63) * 64;
    int t = threadIdx.x, warp = t >> 5, lane = t & 31;

    ((float4*)sw)[t] = ((const float4*)(g_w[c]))[t];
    ((float4*)sacc)[t] = make_float4(0.f, 0.f, 0.f, 0.f);
    if (t == 0) zsh = 0.f;
    float b0 = g_b0[c];
    __syncthreads();

    const float4* fb =
        (const float4*)(feats + ((size_t)c * NPER + base + (size_t)warp * 8) * DIM);

    float4 acc[8];
    #pragma unroll
    for (int k = 0; k < 8; k++) acc[k] = make_float4(0.f, 0.f, 0.f, 0.f);
    float zw = 0.f;

    for (int r = 0; r < 8; r++) {
        float4 f[8];
        #pragma unroll
        for (int k = 0; k < 8; k++)
            f[k] = fb[(size_t)r * 256 + lane + k * 32];

        float d = 0.f;
        #pragma unroll
        for (int k = 0; k < 8; k++) {
            float4 w4 = ((const float4*)sw)[lane + k * 32];
            d += f[k].x * w4.x + f[k].y * w4.y + f[k].z * w4.z + f[k].w * w4.w;
        }
        #pragma unroll
        for (int o = 16; o > 0; o >>= 1)
            d += __shfl_xor_sync(0xffffffffu, d, o);

        float s = (d + b0) * 0.08838834764831845f;  // 1/sqrt(128)
        float e = expf(s);                           // |s| small: safe
        zw += e;

        if (lane == 0) {
            int n = base + warp * 8 + r;
            unsigned u = __float_as_uint(s);
            u = (u & 0x80000000u) ? ~u : (u | 0x80000000u);  // ascending map
            unsigned dm = ~u;                                // descending map
            g_keys[c][n] = ((unsigned long long)dm << 32) | (unsigned)n;
            atomicAdd(&g_hist[c][dm >> (32 - HBITS)], 1u);   // spread bins
        }

        #pragma unroll
        for (int k = 0; k < 8; k++) {
            acc[k].x += e * f[k].x; acc[k].y += e * f[k].y;
            acc[k].z += e * f[k].z; acc[k].w += e * f[k].w;
        }
    }

    // cross-warp combine (serialized rounds)
    for (int wi = 0; wi < 8; wi++) {
        if (warp == wi) {
            #pragma unroll
            for (int k = 0; k < 8; k++) {
                float4* p = &((float4*)sacc)[lane + k * 32];
                float4 v = *p;
                v.x += acc[k].x; v.y += acc[k].y;
                v.z += acc[k].z; v.w += acc[k].w;
                *p = v;
            }
            if (lane == 0) zsh += zw;
        }
        __syncthreads();
    }

    float4 v = ((float4*)sacc)[t];
    float* gp = g_gvec[c] + t * 4;
    atomicAdd(gp + 0, v.x);
    atomicAdd(gp + 1, v.y);
    atomicAdd(gp + 2, v.z);
    atomicAdd(gp + 3, v.w);
    if (t == 0) atomicAdd(&g_Z[c], zw == zw ? zsh : zsh);  // == atomicAdd(zsh)
}

// ---------------------------------------------------------------------------
// Kernel C: exact top-128 via precomputed 12-bit histogram (R12-validated).
// grid = NC, block = 1024.
// ---------------------------------------------------------------------------
__global__ __launch_bounds__(1024) void topk_kernel() {
    __shared__ unsigned warp_tot[32];
    __shared__ unsigned warp_off[32];
    __shared__ unsigned s_B, s_total;
    __shared__ unsigned long long cand[CANDMAX];

    int c = blockIdx.x;
    int t = threadIdx.x;
    int warp = t >> 5, lane = t & 31;

    // ---- 1. histogram scan: find bin B where cumulative count >= 128 ----
    unsigned bins[4];
    {
        uint4 q = ((const uint4*)g_hist[c])[t];
        bins[0] = q.x; bins[1] = q.y; bins[2] = q.z; bins[3] = q.w;
    }
    unsigned loc = bins[0] + bins[1] + bins[2] + bins[3];

    unsigned incl = loc;
    #pragma unroll
    for (int o = 1; o < 32; o <<= 1) {
        unsigned u = __shfl_up_sync(0xffffffffu, incl, o);
        if (lane >= o) incl += u;
    }
    if (lane == 31) warp_tot[warp] = incl;
    __syncthreads();
    if (warp == 0) {
        unsigned v = warp_tot[lane];
        unsigned i2 = v;
        #pragma unroll
        for (int o = 1; o < 32; o <<= 1) {
            unsigned u = __shfl_up_sync(0xffffffffu, i2, o);
            if (lane >= o) i2 += u;
        }
        warp_off[lane] = i2 - v;   // exclusive per-warp offset
    }
    __syncthreads();

    unsigned texcl = warp_off[warp] + incl - loc;  // excl prefix before my bins
    if (texcl < TOPK && texcl + loc >= TOPK) {     // crossing in my 4 bins
        unsigned run = texcl;
        #pragma unroll
        for (int i = 0; i < 4; i++) {
            run += bins[i];
            if (run >= TOPK) { s_B = (unsigned)(t * 4 + i); s_total = run; break; }
        }
    }
    __syncthreads();
    unsigned B = s_B;

    // ---- 2. compact candidates (prefix <= B) via ballot-scan ----
    unsigned long long key[4];
    bool sel[4];
    unsigned laneoff[4];
    unsigned cnt_w = 0u;
    #pragma unroll
    for (int i = 0; i < 4; i++) {
        key[i] = g_keys[c][t + i * 1024];
        sel[i] = ((unsigned)(key[i] >> (64 - HBITS)) <= B);
        unsigned b = __ballot_sync(0xffffffffu, sel[i]);
        laneoff[i] = cnt_w + __popc(b & ((1u << lane) - 1u));
        cnt_w += __popc(b);
    }
    if (lane == 0) warp_tot[warp] = cnt_w;
    __syncthreads();
    if (warp == 0) {
        unsigned v = warp_tot[lane];
        unsigned i2 = v;
        #pragma unroll
        for (int o = 1; o < 32; o <<= 1) {
            unsigned u = __shfl_up_sync(0xffffffffu, i2, o);
            if (lane >= o) i2 += u;
        }
        warp_off[lane] = i2 - v;
    }
    __syncthreads();
    unsigned cbase = warp_off[warp];
    #pragma unroll
    for (int i = 0; i < 4; i++) {
        if (sel[i]) {
            unsigned p = cbase + laneoff[i];
            if (p < CANDMAX) cand[p] = key[i];
        }
    }
    __syncthreads();

    // ---- 3. rank-by-counting (candidate rank == global rank) ----
    unsigned cnt = s_total < CANDMAX ? s_total : CANDMAX;
    if (t < cnt) {
        unsigned long long mine = cand[t];
        unsigned rank = 0u;
        for (unsigned j = 0; j < cnt; j++)
            rank += (cand[j] < mine) ? 1u : 0u;
        if (rank < TOPK)
            g_topidx[c][rank] = (int)(unsigned)(mine & 0xffffffffu);
    }
}

// ---------------------------------------------------------------------------
// Kernel D (merged gather + fusion, REWORKED), block = 256:
//   blocks [0, 512):    gather 2 rows/block, 2 independent float4/thread
//   blocks [512, 640):  fusion TRANSPOSED: warp loads one v_w row ONCE and
//                       dots it vs all 8 clusters' normalized g-vectors
//                       (v_w traffic 32MB -> 4MB).
// ---------------------------------------------------------------------------
__global__ __launch_bounds__(256) void gather_fusion_kernel(
        const float* __restrict__ feats,
        const float* __restrict__ v_w,
        const float* __restrict__ v_b,
        float* __restrict__ out) {
    __shared__ __align__(16) float sg[NC * DIM];   // 32KB: all 8 g-vectors
    int t = threadIdx.x;
    int warp = t >> 5, lane = t & 31;

    if (blockIdx.x < 512) {
        // ---- gather: rows 2b, 2b+1 ----
        int row = blockIdx.x * 2 + (t >> 7);
        int ci = t & 127;
        int c = row >> 7, k = row & 127;
        int src = g_topidx[c][k];
        const float4* s =
            (const float4*)(feats + ((size_t)c * NPER + src) * DIM);
        float4* dst = (float4*)(out + (size_t)row * DIM);
        float4 v0 = s[ci];
        float4 v1 = s[ci + 128];
        dst[ci] = v0;
        dst[ci + 128] = v1;
        return;
    }

    // ---- fusion: this block handles 8 v_w rows x all 8 clusters ----
    int rbase = (int)(blockIdx.x - 512) * 8;       // 128 blocks * 8 rows

    // stage all 8 normalized g-vectors: 2048 float4 / 256 threads = 8 each
    #pragma unroll
    for (int i = 0; i < 8; i++) {
        int idx = t + i * 256;                      // float4 index in [0,2048)
        int cc = idx >> 8;                          // cluster
        float invZ = 1.f / g_Z[cc];
        float4 gv = ((const float4*)(g_gvec[cc]))[idx & 255];
        gv.x *= invZ; gv.y *= invZ; gv.z *= invZ; gv.w *= invZ;
        ((float4*)sg)[idx] = gv;
    }
    __syncthreads();

    int o = rbase + warp;                           // my v_w row
    const float4* vr = (const float4*)(v_w + (size_t)o * DIM);
    float4 f[8];
    #pragma unroll
    for (int k = 0; k < 8; k++)
        f[k] = vr[lane + k * 32];
    float vb = v_b[o];

    #pragma unroll
    for (int cc = 0; cc < NC; cc++) {
        const float4* gr = (const float4*)(sg + cc * DIM);
        float d = 0.f;
        #pragma unroll
        for (int k = 0; k < 8; k++) {
            float4 g4 = gr[lane + k * 32];
            d += f[k].x * g4.x + f[k].y * g4.y + f[k].z * g4.z + f[k].w * g4.w;
        }
        #pragma unroll
        for (int ofs = 16; ofs > 0; ofs >>= 1)
            d += __shfl_xor_sync(0xffffffffu, d, ofs);
        if (lane == 0)
            out[(size_t)1024 * 1024 + (size_t)cc * DIM + o] = d + vb;
    }
}

// ---------------------------------------------------------------------------
extern "C" void kernel_launch(void* const* d_in, const int* in_sizes, int n_in,
                              void* d_out, int out_size) {
    const float* feats     = (const float*)d_in[0];  // [8,4096,1024]
    const float* key_feats = (const float*)d_in[1];  // [8,1,1024]
    const float* q_w       = (const float*)d_in[2];  // [128,1024]
    const float* q_b       = (const float*)d_in[3];  // [128]
    const float* v_w       = (const float*)d_in[4];  // [1024,1024]
    const float* v_b       = (const float*)d_in[5];  // [1024]
    float* out = (float*)d_out;  // selected [1024,1024] then fus [8,1024]

    prep_kernel<<<NC, 1024>>>(key_feats, q_w, q_b);
    fused_pass_kernel<<<NC * 64, 256>>>(feats);
    topk_kernel<<<NC, 1024>>>();
    gather_fusion_kernel<<<640, 256>>>(feats, v_w, v_b, out);  // profiled
}

// round 14
// speedup vs baseline: 1.3800x; 1.0759x over previous
#include <cuda_runtime.h>
#include <math.h>

#define DIM   1024
#define NC    8
#define NPER  4096
#define QDIM  128
#define TOPK  128
#define HBITS 12
#define HBINS (1 << HBITS)      // 4096 bins per cluster
#define CANDMAX 640

// Scratch (no allocations allowed -> __device__ globals)
__device__ float g_w[NC][DIM];                   // q_w^T @ qk per cluster
__device__ float g_b0[NC];                       // q_b . qk
__device__ unsigned long long g_keys[NC][NPER];  // (desc-map(score)<<32)|idx
__device__ unsigned g_hist[NC][HBINS];           // 12-bit key-prefix histogram
__device__ int   g_topidx[NC][TOPK];             // sorted top-k indices
__device__ float g_gvec[NC][DIM];                // sum_n e^{s_n} feats[n]
__device__ float g_Z[NC];                        // sum_n e^{s_n}

// ---------------------------------------------------------------------------
// Kernel A: per-cluster qk = key@q_w^T + q_b ; w = q_w^T @ qk ; b0 = q_b.qk
// Also zeroes g_gvec / g_Z / g_hist. grid = NC, block = 1024. UNCHANGED.
// ---------------------------------------------------------------------------
__global__ __launch_bounds__(1024) void prep_kernel(const float* __restrict__ key_feats,
                                                    const float* __restrict__ q_w,
                                                    const float* __restrict__ q_b) {
    __shared__ __align__(16) float s_qk[QDIM];
    __shared__ float red[4];
    int c = blockIdx.x;
    int t = threadIdx.x;
    int warp = t >> 5, lane = t & 31;

    g_gvec[c][t] = 0.f;          // t covers all DIM=1024
    if (t == 0) g_Z[c] = 0.f;

    // zero this cluster's histogram (4096 bins = 1024 uint4)
    ((uint4*)g_hist[c])[t] = make_uint4(0u, 0u, 0u, 0u);

    const float4* kr = (const float4*)(key_feats + (size_t)c * DIM);
    #pragma unroll
    for (int rr = 0; rr < 4; rr++) {
        int q = warp + rr * 32;
        const float4* qr = (const float4*)(q_w + (size_t)q * DIM);
        float a = 0.f;
        #pragma unroll
        for (int k = 0; k < 8; k++) {
            float4 x = qr[lane + k * 32], y = kr[lane + k * 32];
            a += x.x * y.x + x.y * y.y + x.z * y.z + x.w * y.w;
        }
        #pragma unroll
        for (int o = 16; o > 0; o >>= 1)
            a += __shfl_xor_sync(0xffffffffu, a, o);
        if (lane == 0) s_qk[q] = a + q_b[q];
    }
    __syncthreads();

    float wacc = 0.f;
    #pragma unroll 16
    for (int q = 0; q < QDIM; q++)
        wacc += s_qk[q] * q_w[(size_t)q * DIM + t];
    g_w[c][t] = wacc;

    if (t < QDIM) {
        float p = s_qk[t] * q_b[t];
        #pragma unroll
        for (int o = 16; o > 0; o >>= 1)
            p += __shfl_xor_sync(0xffffffffu, p, o);
        if (lane == 0) red[warp] = p;
    }
    __syncthreads();
    if (t == 0) g_b0[c] = red[0] + red[1] + red[2] + red[3];
}

// ---------------------------------------------------------------------------
// Kernel B: EXACT R9 fused pass (best measured: ~31.9us). UNCHANGED.
// ---------------------------------------------------------------------------
__global__ __launch_bounds__(256) void fused_pass_kernel(const float* __restrict__ feats) {
    __shared__ __align__(16) float sw[DIM];
    __shared__ __align__(16) float sacc[DIM];
    __shared__ float zsh;

    int bid = blockIdx.x;
    int c = bid >> 6;
    int base = (bid & 63) * 64;
    int t = threadIdx.x, warp = t >> 5, lane = t & 31;

    ((float4*)sw)[t] = ((const float4*)(g_w[c]))[t];
    ((float4*)sacc)[t] = make_float4(0.f, 0.f, 0.f, 0.f);
    if (t == 0) zsh = 0.f;
    float b0 = g_b0[c];
    __syncthreads();

    const float4* fb =
        (const float4*)(feats + ((size_t)c * NPER + base + (size_t)warp * 8) * DIM);

    float4 acc[8];
    #pragma unroll
    for (int k = 0; k < 8; k++) acc[k] = make_float4(0.f, 0.f, 0.f, 0.f);
    float zw = 0.f;

    for (int r = 0; r < 8; r++) {
        float4 f[8];
        #pragma unroll
        for (int k = 0; k < 8; k++)
            f[k] = fb[(size_t)r * 256 + lane + k * 32];

        float d = 0.f;
        #pragma unroll
        for (int k = 0; k < 8; k++) {
            float4 w4 = ((const float4*)sw)[lane + k * 32];
            d += f[k].x * w4.x + f[k].y * w4.y + f[k].z * w4.z + f[k].w * w4.w;
        }
        #pragma unroll
        for (int o = 16; o > 0; o >>= 1)
            d += __shfl_xor_sync(0xffffffffu, d, o);

        float s = (d + b0) * 0.08838834764831845f;  // 1/sqrt(128)
        float e = expf(s);                           // |s| small: safe
        zw += e;

        if (lane == 0) {
            int n = base + warp * 8 + r;
            unsigned u = __float_as_uint(s);
            u = (u & 0x80000000u) ? ~u : (u | 0x80000000u);  // ascending map
            unsigned dm = ~u;                                // descending map
            g_keys[c][n] = ((unsigned long long)dm << 32) | (unsigned)n;
            atomicAdd(&g_hist[c][dm >> (32 - HBITS)], 1u);   // spread bins
        }

        #pragma unroll
        for (int k = 0; k < 8; k++) {
            acc[k].x += e * f[k].x; acc[k].y += e * f[k].y;
            acc[k].z += e * f[k].z; acc[k].w += e * f[k].w;
        }
    }

    // cross-warp combine (serialized rounds)
    for (int wi = 0; wi < 8; wi++) {
        if (warp == wi) {
            #pragma unroll
            for (int k = 0; k < 8; k++) {
                float4* p = &((float4*)sacc)[lane + k * 32];
                float4 v = *p;
                v.x += acc[k].x; v.y += acc[k].y;
                v.z += acc[k].z; v.w += acc[k].w;
                *p = v;
            }
            if (lane == 0) zsh += zw;
        }
        __syncthreads();
    }

    float4 v = ((float4*)sacc)[t];
    float* gp = g_gvec[c] + t * 4;
    atomicAdd(gp + 0, v.x);
    atomicAdd(gp + 1, v.y);
    atomicAdd(gp + 2, v.z);
    atomicAdd(gp + 3, v.w);
    if (t == 0) atomicAdd(&g_Z[c], zsh);
}

// ---------------------------------------------------------------------------
// Kernel C (merged topk + fusion), grid = NC + 32, block = 1024:
//   blocks [0, NC):    exact top-128 via 12-bit histogram (R12-validated)
//   blocks [NC, NC+32): transposed fusion — warp loads one v_w row ONCE,
//                       dots vs all 8 smem-staged normalized g-vectors.
//                       Runs on SMs idle during topk (only 8 topk blocks).
// ---------------------------------------------------------------------------
__global__ __launch_bounds__(1024) void topk_fusion_kernel(
        const float* __restrict__ v_w,
        const float* __restrict__ v_b,
        float* __restrict__ out) {
    __shared__ __align__(16) float sg[NC * DIM];   // 32KB (fusion blocks)
    __shared__ unsigned warp_tot[32];
    __shared__ unsigned warp_off[32];
    __shared__ unsigned s_B, s_total;
    __shared__ unsigned long long cand[CANDMAX];

    int t = threadIdx.x;
    int warp = t >> 5, lane = t & 31;

    if (blockIdx.x >= NC) {
        // ---------------- fusion (32 blocks x 32 warps = 1024 rows) -------
        int rbase = (int)(blockIdx.x - NC) * 32;

        // stage all 8 normalized g-vectors: 2048 float4 / 1024 threads = 2
        #pragma unroll
        for (int i = 0; i < 2; i++) {
            int idx = t + i * 1024;                 // float4 index [0,2048)
            int cc = idx >> 8;
            float invZ = 1.f / g_Z[cc];
            float4 gv = ((const float4*)(g_gvec[cc]))[idx & 255];
            gv.x *= invZ; gv.y *= invZ; gv.z *= invZ; gv.w *= invZ;
            ((float4*)sg)[idx] = gv;
        }
        __syncthreads();

        int o = rbase + warp;                       // my v_w row
        const float4* vr = (const float4*)(v_w + (size_t)o * DIM);
        float4 f[8];
        #pragma unroll
        for (int k = 0; k < 8; k++)
            f[k] = vr[lane + k * 32];
        float vb = v_b[o];

        #pragma unroll
        for (int cc = 0; cc < NC; cc++) {
            const float4* gr = (const float4*)(sg + cc * DIM);
            float d = 0.f;
            #pragma unroll
            for (int k = 0; k < 8; k++) {
                float4 g4 = gr[lane + k * 32];
                d += f[k].x * g4.x + f[k].y * g4.y
                   + f[k].z * g4.z + f[k].w * g4.w;
            }
            #pragma unroll
            for (int ofs = 16; ofs > 0; ofs >>= 1)
                d += __shfl_xor_sync(0xffffffffu, d, ofs);
            if (lane == 0)
                out[(size_t)1024 * 1024 + (size_t)cc * DIM + o] = d + vb;
        }
        return;
    }

    // ---------------- topk (8 blocks) ----------------
    int c = blockIdx.x;

    // ---- 1. histogram scan: find bin B where cumulative count >= 128 ----
    unsigned bins[4];
    {
        uint4 q = ((const uint4*)g_hist[c])[t];
        bins[0] = q.x; bins[1] = q.y; bins[2] = q.z; bins[3] = q.w;
    }
    unsigned loc = bins[0] + bins[1] + bins[2] + bins[3];

    unsigned incl = loc;
    #pragma unroll
    for (int o = 1; o < 32; o <<= 1) {
        unsigned u = __shfl_up_sync(0xffffffffu, incl, o);
        if (lane >= o) incl += u;
    }
    if (lane == 31) warp_tot[warp] = incl;
    __syncthreads();
    if (warp == 0) {
        unsigned v = warp_tot[lane];
        unsigned i2 = v;
        #pragma unroll
        for (int o = 1; o < 32; o <<= 1) {
            unsigned u = __shfl_up_sync(0xffffffffu, i2, o);
            if (lane >= o) i2 += u;
        }
        warp_off[lane] = i2 - v;   // exclusive per-warp offset
    }
    __syncthreads();

    unsigned texcl = warp_off[warp] + incl - loc;  // excl prefix before my bins
    if (texcl < TOPK && texcl + loc >= TOPK) {     // crossing in my 4 bins
        unsigned run = texcl;
        #pragma unroll
        for (int i = 0; i < 4; i++) {
            run += bins[i];
            if (run >= TOPK) { s_B = (unsigned)(t * 4 + i); s_total = run; break; }
        }
    }
    __syncthreads();
    unsigned B = s_B;

    // ---- 2. compact candidates (prefix <= B) via ballot-scan ----
    unsigned long long key[4];
    bool sel[4];
    unsigned laneoff[4];
    unsigned cnt_w = 0u;
    #pragma unroll
    for (int i = 0; i < 4; i++) {
        key[i] = g_keys[c][t + i * 1024];
        sel[i] = ((unsigned)(key[i] >> (64 - HBITS)) <= B);
        unsigned b = __ballot_sync(0xffffffffu, sel[i]);
        laneoff[i] = cnt_w + __popc(b & ((1u << lane) - 1u));
        cnt_w += __popc(b);
    }
    if (lane == 0) warp_tot[warp] = cnt_w;
    __syncthreads();
    if (warp == 0) {
        unsigned v = warp_tot[lane];
        unsigned i2 = v;
        #pragma unroll
        for (int o = 1; o < 32; o <<= 1) {
            unsigned u = __shfl_up_sync(0xffffffffu, i2, o);
            if (lane >= o) i2 += u;
        }
        warp_off[lane] = i2 - v;
    }
    __syncthreads();
    unsigned cbase = warp_off[warp];
    #pragma unroll
    for (int i = 0; i < 4; i++) {
        if (sel[i]) {
            unsigned p = cbase + laneoff[i];
            if (p < CANDMAX) cand[p] = key[i];
        }
    }
    __syncthreads();

    // ---- 3. rank-by-counting (candidate rank == global rank) ----
    unsigned cnt = s_total < CANDMAX ? s_total : CANDMAX;
    if (t < cnt) {
        unsigned long long mine = cand[t];
        unsigned rank = 0u;
        for (unsigned j = 0; j < cnt; j++)
            rank += (cand[j] < mine) ? 1u : 0u;
        if (rank < TOPK)
            g_topidx[c][rank] = (int)(unsigned)(mine & 0xffffffffu);
    }
}

// ---------------------------------------------------------------------------
// Kernel D: gather, best-measured config (grid 1024, block 256, no smem).
// ---------------------------------------------------------------------------
__global__ void gather_kernel(const float* __restrict__ feats,
                              float* __restrict__ out) {
    int row = blockIdx.x;
    int c = row >> 7, k = row & 127;
    int src = g_topidx[c][k];
    const float4* s = (const float4*)(feats + ((size_t)c * NPER + src) * DIM);
    float4* dst = (float4*)(out + (size_t)row * DIM);
    dst[threadIdx.x] = s[threadIdx.x];
}

// ---------------------------------------------------------------------------
extern "C" void kernel_launch(void* const* d_in, const int* in_sizes, int n_in,
                              void* d_out, int out_size) {
    const float* feats     = (const float*)d_in[0];  // [8,4096,1024]
    const float* key_feats = (const float*)d_in[1];  // [8,1,1024]
    const float* q_w       = (const float*)d_in[2];  // [128,1024]
    const float* q_b       = (const float*)d_in[3];  // [128]
    const float* v_w       = (const float*)d_in[4];  // [1024,1024]
    const float* v_b       = (const float*)d_in[5];  // [1024]
    float* out = (float*)d_out;  // selected [1024,1024] then fus [8,1024]

    prep_kernel<<<NC, 1024>>>(key_feats, q_w, q_b);
    fused_pass_kernel<<<NC * 64, 256>>>(feats);
    topk_fusion_kernel<<<NC + 32, 1024>>>(v_w, v_b, out);
    gather_kernel<<<1024, 256>>>(feats, out);   // <- profiled this round
}

// round 15
// speedup vs baseline: 1.4415x; 1.0446x over previous
#include <cuda_runtime.h>
#include <math.h>

#define DIM   1024
#define NC    8
#define NPER  4096
#define QDIM  128
#define TOPK  128
#define HBITS 12
#define HBINS (1 << HBITS)      // 4096 bins per cluster
#define CANDMAX 640

// Scratch (no allocations allowed -> __device__ globals)
__device__ float g_w[NC][DIM];                   // q_w^T @ qk per cluster
__device__ float g_b0[NC];                       // q_b . qk
__device__ unsigned long long g_keys[NC][NPER];  // (desc-map(score)<<32)|idx
__device__ unsigned g_hist[NC][HBINS];           // 12-bit key-prefix histogram
__device__ int   g_topidx[NC][TOPK];             // sorted top-k indices
__device__ float g_gvec[NC][DIM];                // sum_n e^{s_n} feats[n]
__device__ float g_Z[NC];                        // sum_n e^{s_n}
__device__ unsigned g_flag[NC];                  // topidx-ready flags

// ---------------------------------------------------------------------------
// Kernel A: per-cluster qk = key@q_w^T + q_b ; w = q_w^T @ qk ; b0 = q_b.qk
// Also zeroes g_gvec / g_Z / g_hist / g_flag. grid = NC, block = 1024.
// ---------------------------------------------------------------------------
__global__ __launch_bounds__(1024) void prep_kernel(const float* __restrict__ key_feats,
                                                    const float* __restrict__ q_w,
                                                    const float* __restrict__ q_b) {
    __shared__ __align__(16) float s_qk[QDIM];
    __shared__ float red[4];
    int c = blockIdx.x;
    int t = threadIdx.x;
    int warp = t >> 5, lane = t & 31;

    g_gvec[c][t] = 0.f;          // t covers all DIM=1024
    if (t == 0) { g_Z[c] = 0.f; g_flag[c] = 0u; }

    // zero this cluster's histogram (4096 bins = 1024 uint4)
    ((uint4*)g_hist[c])[t] = make_uint4(0u, 0u, 0u, 0u);

    const float4* kr = (const float4*)(key_feats + (size_t)c * DIM);
    #pragma unroll
    for (int rr = 0; rr < 4; rr++) {
        int q = warp + rr * 32;
        const float4* qr = (const float4*)(q_w + (size_t)q * DIM);
        float a = 0.f;
        #pragma unroll
        for (int k = 0; k < 8; k++) {
            float4 x = qr[lane + k * 32], y = kr[lane + k * 32];
            a += x.x * y.x + x.y * y.y + x.z * y.z + x.w * y.w;
        }
        #pragma unroll
        for (int o = 16; o > 0; o >>= 1)
            a += __shfl_xor_sync(0xffffffffu, a, o);
        if (lane == 0) s_qk[q] = a + q_b[q];
    }
    __syncthreads();

    float wacc = 0.f;
    #pragma unroll 16
    for (int q = 0; q < QDIM; q++)
        wacc += s_qk[q] * q_w[(size_t)q * DIM + t];
    g_w[c][t] = wacc;

    if (t < QDIM) {
        float p = s_qk[t] * q_b[t];
        #pragma unroll
        for (int o = 16; o > 0; o >>= 1)
            p += __shfl_xor_sync(0xffffffffu, p, o);
        if (lane == 0) red[warp] = p;
    }
    __syncthreads();
    if (t == 0) g_b0[c] = red[0] + red[1] + red[2] + red[3];
}

// ---------------------------------------------------------------------------
// Kernel B: R9 inner structure, SINGLE-WAVE grid: 256 blocks x 128 rows
// (2 CTAs/SM x 148 SMs = 296 capacity >= 256 -> all blocks co-resident,
// no ragged second wave). Warp owns 16 rows; 8 float4/lane per row.
// ---------------------------------------------------------------------------
__global__ __launch_bounds__(256) void fused_pass_kernel(const float* __restrict__ feats) {
    __shared__ __align__(16) float sw[DIM];
    __shared__ __align__(16) float sacc[DIM];
    __shared__ float zsh;

    int bid = blockIdx.x;
    int c = bid >> 5;                    // 32 blocks per cluster
    int base = (bid & 31) * 128;
    int t = threadIdx.x, warp = t >> 5, lane = t & 31;

    ((float4*)sw)[t] = ((const float4*)(g_w[c]))[t];
    ((float4*)sacc)[t] = make_float4(0.f, 0.f, 0.f, 0.f);
    if (t == 0) zsh = 0.f;
    float b0 = g_b0[c];
    __syncthreads();

    const float4* fb =
        (const float4*)(feats + ((size_t)c * NPER + base + (size_t)warp * 16) * DIM);

    float4 acc[8];
    #pragma unroll
    for (int k = 0; k < 8; k++) acc[k] = make_float4(0.f, 0.f, 0.f, 0.f);
    float zw = 0.f;

    for (int r = 0; r < 16; r++) {
        float4 f[8];
        #pragma unroll
        for (int k = 0; k < 8; k++)
            f[k] = fb[(size_t)r * 256 + lane + k * 32];

        float d = 0.f;
        #pragma unroll
        for (int k = 0; k < 8; k++) {
            float4 w4 = ((const float4*)sw)[lane + k * 32];
            d += f[k].x * w4.x + f[k].y * w4.y + f[k].z * w4.z + f[k].w * w4.w;
        }
        #pragma unroll
        for (int o = 16; o > 0; o >>= 1)
            d += __shfl_xor_sync(0xffffffffu, d, o);

        float s = (d + b0) * 0.08838834764831845f;  // 1/sqrt(128)
        float e = expf(s);                           // |s| small: safe
        zw += e;

        if (lane == 0) {
            int n = base + warp * 16 + r;
            unsigned u = __float_as_uint(s);
            u = (u & 0x80000000u) ? ~u : (u | 0x80000000u);  // ascending map
            unsigned dm = ~u;                                // descending map
            g_keys[c][n] = ((unsigned long long)dm << 32) | (unsigned)n;
            atomicAdd(&g_hist[c][dm >> (32 - HBITS)], 1u);   // spread bins
        }

        #pragma unroll
        for (int k = 0; k < 8; k++) {
            acc[k].x += e * f[k].x; acc[k].y += e * f[k].y;
            acc[k].z += e * f[k].z; acc[k].w += e * f[k].w;
        }
    }

    // cross-warp combine (serialized rounds)
    for (int wi = 0; wi < 8; wi++) {
        if (warp == wi) {
            #pragma unroll
            for (int k = 0; k < 8; k++) {
                float4* p = &((float4*)sacc)[lane + k * 32];
                float4 v = *p;
                v.x += acc[k].x; v.y += acc[k].y;
                v.z += acc[k].z; v.w += acc[k].w;
                *p = v;
            }
            if (lane == 0) zsh += zw;
        }
        __syncthreads();
    }

    float4 v = ((float4*)sacc)[t];
    float* gp = g_gvec[c] + t * 4;
    atomicAdd(gp + 0, v.x);
    atomicAdd(gp + 1, v.y);
    atomicAdd(gp + 2, v.z);
    atomicAdd(gp + 3, v.w);
    if (t == 0) atomicAdd(&g_Z[c], zsh);
}

// ---------------------------------------------------------------------------
// Kernel C (merged topk + fusion + gather), grid = NC + 32 + 256 = 296,
// block = 1024:
//   blocks [0, NC):          topk -> g_topidx[c], then release g_flag[c]
//   blocks [NC, NC+32):      transposed fusion (hidden under topk)
//   blocks [NC+32, NC+32+256): gather 4 rows/block, acquire-spin on flag.
// Deadlock-safe: topk blocks have the lowest IDs -> wave-1 residents.
// ---------------------------------------------------------------------------
__global__ __launch_bounds__(1024) void topk_fusion_gather_kernel(
        const float* __restrict__ feats,
        const float* __restrict__ v_w,
        const float* __restrict__ v_b,
        float* __restrict__ out) {
    __shared__ __align__(16) float sg[NC * DIM];   // 32KB (fusion blocks)
    __shared__ unsigned warp_tot[32];
    __shared__ unsigned warp_off[32];
    __shared__ unsigned s_B, s_total;
    __shared__ unsigned long long cand[CANDMAX];

    int t = threadIdx.x;
    int warp = t >> 5, lane = t & 31;

    if (blockIdx.x >= NC + 32) {
        // ---------------- gather (256 blocks x 4 rows) ----------------
        int g = (int)blockIdx.x - (NC + 32);
        int row = g * 4 + (t >> 8);
        int c = row >> 7, k = row & 127;

        if (t == 0) {
            while (atomicAdd(&g_flag[c], 0u) == 0u)
                __nanosleep(64);
        }
        __syncthreads();
        __threadfence();

        int src = g_topidx[c][k];
        int ci = t & 255;
        const float4* s =
            (const float4*)(feats + ((size_t)c * NPER + src) * DIM);
        float4* dst = (float4*)(out + (size_t)row * DIM);
        dst[ci] = s[ci];
        return;
    }

    if (blockIdx.x >= NC) {
        // ---------------- fusion (32 blocks x 32 warps = 1024 rows) -------
        int rbase = (int)(blockIdx.x - NC) * 32;

        #pragma unroll
        for (int i = 0; i < 2; i++) {
            int idx = t + i * 1024;                 // float4 index [0,2048)
            int cc = idx >> 8;
            float invZ = 1.f / g_Z[cc];
            float4 gv = ((const float4*)(g_gvec[cc]))[idx & 255];
            gv.x *= invZ; gv.y *= invZ; gv.z *= invZ; gv.w *= invZ;
            ((float4*)sg)[idx] = gv;
        }
        __syncthreads();

        int o = rbase + warp;                       // my v_w row
        const float4* vr = (const float4*)(v_w + (size_t)o * DIM);
        float4 f[8];
        #pragma unroll
        for (int k = 0; k < 8; k++)
            f[k] = vr[lane + k * 32];
        float vb = v_b[o];

        #pragma unroll
        for (int cc = 0; cc < NC; cc++) {
            const float4* gr = (const float4*)(sg + cc * DIM);
            float d = 0.f;
            #pragma unroll
            for (int k = 0; k < 8; k++) {
                float4 g4 = gr[lane + k * 32];
                d += f[k].x * g4.x + f[k].y * g4.y
                   + f[k].z * g4.z + f[k].w * g4.w;
            }
            #pragma unroll
            for (int ofs = 16; ofs > 0; ofs >>= 1)
                d += __shfl_xor_sync(0xffffffffu, d, ofs);
            if (lane == 0)
                out[(size_t)1024 * 1024 + (size_t)cc * DIM + o] = d + vb;
        }
        return;
    }

    // ---------------- topk (8 blocks) ----------------
    int c = blockIdx.x;

    // ---- 1. histogram scan: find bin B where cumulative count >= 128 ----
    unsigned bins[4];
    {
        uint4 q = ((const uint4*)g_hist[c])[t];
        bins[0] = q.x; bins[1] = q.y; bins[2] = q.z; bins[3] = q.w;
    }
    unsigned loc = bins[0] + bins[1] + bins[2] + bins[3];

    unsigned incl = loc;
    #pragma unroll
    for (int o = 1; o < 32; o <<= 1) {
        unsigned u = __shfl_up_sync(0xffffffffu, incl, o);
        if (lane >= o) incl += u;
    }
    if (lane == 31) warp_tot[warp] = incl;
    __syncthreads();
    if (warp == 0) {
        unsigned v = warp_tot[lane];
        unsigned i2 = v;
        #pragma unroll
        for (int o = 1; o < 32; o <<= 1) {
            unsigned u = __shfl_up_sync(0xffffffffu, i2, o);
            if (lane >= o) i2 += u;
        }
        warp_off[lane] = i2 - v;   // exclusive per-warp offset
    }
    __syncthreads();

    unsigned texcl = warp_off[warp] + incl - loc;  // excl prefix before my bins
    if (texcl < TOPK && texcl + loc >= TOPK) {     // crossing in my 4 bins
        unsigned run = texcl;
        #pragma unroll
        for (int i = 0; i < 4; i++) {
            run += bins[i];
            if (run >= TOPK) { s_B = (unsigned)(t * 4 + i); s_total = run; break; }
        }
    }
    __syncthreads();
    unsigned B = s_B;

    // ---- 2. compact candidates (prefix <= B) via ballot-scan ----
    unsigned long long key[4];
    bool sel[4];
    unsigned laneoff[4];
    unsigned cnt_w = 0u;
    #pragma unroll
    for (int i = 0; i < 4; i++) {
        key[i] = g_keys[c][t + i * 1024];
        sel[i] = ((unsigned)(key[i] >> (64 - HBITS)) <= B);
        unsigned b = __ballot_sync(0xffffffffu, sel[i]);
        laneoff[i] = cnt_w + __popc(b & ((1u << lane) - 1u));
        cnt_w += __popc(b);
    }
    if (lane == 0) warp_tot[warp] = cnt_w;
    __syncthreads();
    if (warp == 0) {
        unsigned v = warp_tot[lane];
        unsigned i2 = v;
        #pragma unroll
        for (int o = 1; o < 32; o <<= 1) {
            unsigned u = __shfl_up_sync(0xffffffffu, i2, o);
            if (lane >= o) i2 += u;
        }
        warp_off[lane] = i2 - v;
    }
    __syncthreads();
    unsigned cbase = warp_off[warp];
    #pragma unroll
    for (int i = 0; i < 4; i++) {
        if (sel[i]) {
            unsigned p = cbase + laneoff[i];
            if (p < CANDMAX) cand[p] = key[i];
        }
    }
    __syncthreads();

    // ---- 3. rank-by-counting (candidate rank == global rank) ----
    unsigned cnt = s_total < CANDMAX ? s_total : CANDMAX;
    if (t < cnt) {
        unsigned long long mine = cand[t];
        unsigned rank = 0u;
        for (unsigned j = 0; j < cnt; j++)
            rank += (cand[j] < mine) ? 1u : 0u;
        if (rank < TOPK)
            g_topidx[c][rank] = (int)(unsigned)(mine & 0xffffffffu);
    }

    // ---- 4. release: publish topidx to gather blocks ----
    __syncthreads();
    __threadfence();
    if (t == 0) atomicExch(&g_flag[c], 1u);
}

// ---------------------------------------------------------------------------
extern "C" void kernel_launch(void* const* d_in, const int* in_sizes, int n_in,
                              void* d_out, int out_size) {
    const float* feats     = (const float*)d_in[0];  // [8,4096,1024]
    const float* key_feats = (const float*)d_in[1];  // [8,1,1024]
    const float* q_w       = (const float*)d_in[2];  // [128,1024]
    const float* q_b       = (const float*)d_in[3];  // [128]
    const float* v_w       = (const float*)d_in[4];  // [1024,1024]
    const float* v_b       = (const float*)d_in[5];  // [1024]
    float* out = (float*)d_out;  // selected [1024,1024] then fus [8,1024]

    prep_kernel<<<NC, 1024>>>(key_feats, q_w, q_b);
    fused_pass_kernel<<<NC * 32, 256>>>(feats);   // single wave, 128 rows/blk
    topk_fusion_gather_kernel<<<NC + 32 + 256, 1024>>>(feats, v_w, v_b, out);
}